// round 2
// baseline (speedup 1.0000x reference)
#include <cuda_runtime.h>
#include <math.h>
#include <float.h>

#define NROWS 8192
#define FDIM 256
#define NCLS 64
#define KNNK 5
#define MAXSTEPS 100

// ---------------- device scratch (static: no allocation allowed) ----------------
__device__ float  g_fn[NROWS * FDIM];                 // normalized feats
__device__ float  g_sq[NROWS];                        // sum(fn^2) per row
__device__ float  g_dots[(size_t)NROWS * NROWS];      // f @ f^T  (256 MB)
__device__ float  g_unary[NROWS * NCLS];
__device__ float  g_Ya[NROWS * NCLS];
__device__ float  g_Yb[NROWS * NCLS];
__device__ int    g_idx[NROWS * KNNK];
__device__ double g_Erow[NROWS];
__device__ double g_Eprev;
__device__ int    g_conv;
__device__ int    g_finalIt;

// ---------------- init ----------------
__global__ void init_kernel() {
    g_conv = 0;
    g_finalIt = MAXSTEPS - 1;
    g_Eprev = __longlong_as_double(0x7FF0000000000000LL); // +inf
}

// ---------------- normalize feats, compute sq ----------------
__global__ void normalize_kernel(const float* __restrict__ feats) {
    int row = blockIdx.x;
    int t = threadIdx.x;
    __shared__ float red[8];
    float x = feats[row * FDIM + t];
    float v = x * x;
    #pragma unroll
    for (int o = 16; o; o >>= 1) v += __shfl_xor_sync(0xffffffffu, v, o);
    if ((t & 31) == 0) red[t >> 5] = v;
    __syncthreads();
    float tot = red[0] + red[1] + red[2] + red[3] + red[4] + red[5] + red[6] + red[7];
    float y = x / fmaxf(sqrtf(tot), 1e-12f);
    g_fn[row * FDIM + t] = y;
    float v2 = y * y;
    #pragma unroll
    for (int o = 16; o; o >>= 1) v2 += __shfl_xor_sync(0xffffffffu, v2, o);
    __syncthreads();
    if ((t & 31) == 0) red[t >> 5] = v2;
    __syncthreads();
    if (t == 0)
        g_sq[row] = red[0] + red[1] + red[2] + red[3] + red[4] + red[5] + red[6] + red[7];
}

// ---------------- unary + Y0 (softmax of -unary) ----------------
__global__ void unary_y0_kernel(const float* __restrict__ scores) {
    int w = blockIdx.x * (blockDim.x >> 5) + (threadIdx.x >> 5);
    int lane = threadIdx.x & 31;
    if (w >= NROWS) return;
    float2 s = *(const float2*)(scores + w * NCLS + lane * 2);
    float u0 = -logf(s.x + 1e-10f);
    float u1 = -logf(s.y + 1e-10f);
    *(float2*)(g_unary + w * NCLS + lane * 2) = make_float2(u0, u1);
    float z0 = -u0, z1 = -u1;
    float m = fmaxf(z0, z1);
    #pragma unroll
    for (int o = 16; o; o >>= 1) m = fmaxf(m, __shfl_xor_sync(0xffffffffu, m, o));
    float e0 = expf(z0 - m), e1 = expf(z1 - m);
    float sm = e0 + e1;
    #pragma unroll
    for (int o = 16; o; o >>= 1) sm += __shfl_xor_sync(0xffffffffu, sm, o);
    float inv = 1.f / sm;
    *(float2*)(g_Ya + w * NCLS + lane * 2) = make_float2(e0 * inv, e1 * inv);
}

// ---------------- symmetric GEMM: g_dots = fn @ fn^T ----------------
#define BM 128
#define BK 16
#define NBLK (NROWS / BM) // 64

__global__ void __launch_bounds__(256) gemm_sym_kernel() {
    __shared__ float pool[4224]; // max(2*16*132, 32*132)
    float (*As)[132] = (float(*)[132])pool;
    float (*Bs)[132] = (float(*)[132])(pool + 16 * 132);

    // decode triangular block index
    int t = blockIdx.x;
    int bi = 0;
    while (t >= NBLK - bi) { t -= NBLK - bi; bi++; }
    int bj = bi + t;
    int iBase = bi * BM, jBase = bj * BM;

    int tid = threadIdx.x;
    int tx = tid & 15, ty = tid >> 4;
    int lr = tid >> 2;          // 0..63
    int lc = (tid & 3) * 4;     // 0,4,8,12

    float acc[8][8];
    #pragma unroll
    for (int i = 0; i < 8; ++i)
        #pragma unroll
        for (int j = 0; j < 8; ++j) acc[i][j] = 0.f;

    const float* __restrict__ A = g_fn;

    for (int k0 = 0; k0 < FDIM; k0 += BK) {
        #pragma unroll
        for (int h = 0; h < 2; ++h) {
            int r = lr + h * 64;
            float4 va = *(const float4*)(A + (size_t)(iBase + r) * FDIM + k0 + lc);
            As[lc + 0][r] = va.x; As[lc + 1][r] = va.y;
            As[lc + 2][r] = va.z; As[lc + 3][r] = va.w;
            float4 vb = *(const float4*)(A + (size_t)(jBase + r) * FDIM + k0 + lc);
            Bs[lc + 0][r] = vb.x; Bs[lc + 1][r] = vb.y;
            Bs[lc + 2][r] = vb.z; Bs[lc + 3][r] = vb.w;
        }
        __syncthreads();
        #pragma unroll
        for (int k = 0; k < BK; ++k) {
            float a[8], b[8];
            *(float4*)(a)     = *(const float4*)&As[k][ty * 4];
            *(float4*)(a + 4) = *(const float4*)&As[k][64 + ty * 4];
            *(float4*)(b)     = *(const float4*)&Bs[k][tx * 4];
            *(float4*)(b + 4) = *(const float4*)&Bs[k][64 + tx * 4];
            #pragma unroll
            for (int i = 0; i < 8; ++i)
                #pragma unroll
                for (int j = 0; j < 8; ++j)
                    acc[i][j] += a[i] * b[j];
        }
        __syncthreads();
    }

    // write own tile
    const size_t ld = NROWS;
    #pragma unroll
    for (int ri = 0; ri < 8; ++ri) {
        int r = iBase + ((ri < 4) ? (ty * 4 + ri) : (64 + ty * 4 + ri - 4));
        *(float4*)(g_dots + (size_t)r * ld + jBase + tx * 4) =
            make_float4(acc[ri][0], acc[ri][1], acc[ri][2], acc[ri][3]);
        *(float4*)(g_dots + (size_t)r * ld + jBase + 64 + tx * 4) =
            make_float4(acc[ri][4], acc[ri][5], acc[ri][6], acc[ri][7]);
    }

    // mirror transposed tile via smem staging (32-col chunks)
    if (bi != bj) {
        float (*Cs)[132] = (float(*)[132])pool;
        #pragma unroll
        for (int cc = 0; cc < 4; ++cc) {
            __syncthreads();
            if ((tx >> 3) == cc) { // first col group: cols tx*4..tx*4+3
                #pragma unroll
                for (int ci = 0; ci < 4; ++ci)
                    #pragma unroll
                    for (int ri = 0; ri < 8; ++ri) {
                        int rowLoc = (ri < 4) ? (ty * 4 + ri) : (64 + ty * 4 + ri - 4);
                        Cs[tx * 4 + ci - cc * 32][rowLoc] = acc[ri][ci];
                    }
            }
            if (((tx >> 3) + 2) == cc) { // second col group: 64+tx*4..
                #pragma unroll
                for (int ci = 0; ci < 4; ++ci)
                    #pragma unroll
                    for (int ri = 0; ri < 8; ++ri) {
                        int rowLoc = (ri < 4) ? (ty * 4 + ri) : (64 + ty * 4 + ri - 4);
                        Cs[64 + tx * 4 + ci - cc * 32][rowLoc] = acc[ri][4 + ci];
                    }
            }
            __syncthreads();
            #pragma unroll
            for (int q = 0; q < 4; ++q) {
                int idx = tid + q * 256;
                int rr = idx >> 5;
                int c4 = (idx & 31) * 4;
                float4 v = make_float4(Cs[rr][c4], Cs[rr][c4 + 1], Cs[rr][c4 + 2], Cs[rr][c4 + 3]);
                *(float4*)(g_dots + (size_t)(jBase + cc * 32 + rr) * ld + iBase + c4) = v;
            }
        }
    }
}

// ---------------- top-6 smallest dist per row (tie-break: lower index) ----------------
__device__ __forceinline__ bool cless(float v1, int i1, float v2, int i2) {
    return (v1 < v2) || (v1 == v2 && i1 < i2);
}

__global__ void __launch_bounds__(256) topk_kernel() {
    int row = blockIdx.x;
    int t = threadIdx.x;
    float sqi = g_sq[row];
    const float* __restrict__ drow = g_dots + (size_t)row * NROWS;
    const float* __restrict__ sq = g_sq;

    float bv[6]; int bx[6];
    #pragma unroll
    for (int k = 0; k < 6; ++k) { bv[k] = FLT_MAX; bx[k] = 0x7fffffff; }

    for (int j = t; j < NROWS; j += 256) {
        float d = fmaxf(sqi + sq[j] - 2.f * drow[j], 0.f);
        if (cless(d, j, bv[5], bx[5])) {
            bv[5] = d; bx[5] = j;
            #pragma unroll
            for (int k = 5; k > 0; --k) {
                bool sw = cless(bv[k], bx[k], bv[k - 1], bx[k - 1]);
                float tv = bv[k - 1]; int ti = bx[k - 1];
                bv[k - 1] = sw ? bv[k] : bv[k - 1];
                bx[k - 1] = sw ? bx[k] : bx[k - 1];
                bv[k] = sw ? tv : bv[k];
                bx[k] = sw ? ti : bx[k];
            }
        }
    }

    __shared__ float sv[2][256 * 6];
    __shared__ int   si[2][256 * 6];
    #pragma unroll
    for (int k = 0; k < 6; ++k) { sv[0][t * 6 + k] = bv[k]; si[0][t * 6 + k] = bx[k]; }

    int cur = 0;
    for (int s = 128; s >= 1; s >>= 1) {
        __syncthreads();
        if (t < s) {
            const float* Av = &sv[cur][t * 6];       const int* Ai = &si[cur][t * 6];
            const float* Bv = &sv[cur][(t + s) * 6]; const int* Bi = &si[cur][(t + s) * 6];
            float* Ov = &sv[cur ^ 1][t * 6];         int* Oi = &si[cur ^ 1][t * 6];
            int p = 0, q = 0;
            #pragma unroll
            for (int r = 0; r < 6; ++r) {
                float av = Av[p]; int ai = Ai[p];
                float bw = Bv[q]; int bi2 = Bi[q];
                if (cless(av, ai, bw, bi2)) { Ov[r] = av; Oi[r] = ai; ++p; }
                else                        { Ov[r] = bw; Oi[r] = bi2; ++q; }
            }
        }
        cur ^= 1;
    }
    __syncthreads();
    if (t == 0) {
        #pragma unroll
        for (int r = 1; r <= KNNK; ++r)
            g_idx[row * KNNK + r - 1] = si[cur][r]; // rank 0 is self
    }
}

// ---------------- one mean-field iteration (warp per row) ----------------
__global__ void __launch_bounds__(256) iterA_kernel(int it) {
    if (g_conv) return;
    int row = blockIdx.x * 8 + (threadIdx.x >> 5);
    int lane = threadIdx.x & 31;
    const float* __restrict__ Yold = (it & 1) ? g_Yb : g_Ya;
    float* __restrict__ Ynew = (it & 1) ? g_Ya : g_Yb;

    const int* nb = &g_idx[row * KNNK];
    int n0 = nb[0], n1 = nb[1], n2 = nb[2], n3 = nb[3], n4 = nb[4];

    float2 u = *(const float2*)&g_unary[row * NCLS + lane * 2];
    float2 p0 = *(const float2*)&Yold[n0 * NCLS + lane * 2];
    float2 p1 = *(const float2*)&Yold[n1 * NCLS + lane * 2];
    float2 p2 = *(const float2*)&Yold[n2 * NCLS + lane * 2];
    float2 p3 = *(const float2*)&Yold[n3 * NCLS + lane * 2];
    float2 p4 = *(const float2*)&Yold[n4 * NCLS + lane * 2];
    float pw0 = p0.x + p1.x + p2.x + p3.x + p4.x; // LAM = 1
    float pw1 = p0.y + p1.y + p2.y + p3.y + p4.y;

    float z0 = -u.x + pw0;
    float z1 = -u.y + pw1;
    float m = fmaxf(z0, z1);
    #pragma unroll
    for (int o = 16; o; o >>= 1) m = fmaxf(m, __shfl_xor_sync(0xffffffffu, m, o));
    float e0 = expf(z0 - m), e1 = expf(z1 - m);
    float sm = e0 + e1;
    #pragma unroll
    for (int o = 16; o; o >>= 1) sm += __shfl_xor_sync(0xffffffffu, sm, o);
    float inv = 1.f / sm;
    *(float2*)&Ynew[row * NCLS + lane * 2] = make_float2(e0 * inv, e1 * inv);

    // E_row = -logsumexp(z)  (energy collapses algebraically; LAM=1)
    if (lane == 0) g_Erow[row] = -(double)(m + logf(sm));
}

// ---------------- deterministic energy reduce + convergence check ----------------
__global__ void __launch_bounds__(256) iterB_kernel(int it) {
    if (g_conv) return;
    int t = threadIdx.x;
    double acc = 0.0;
    #pragma unroll
    for (int j = 0; j < 32; ++j) acc += g_Erow[t + 256 * j];
    #pragma unroll
    for (int o = 16; o; o >>= 1) acc += __shfl_xor_sync(0xffffffffu, acc, o);
    __shared__ double red[8];
    if ((t & 31) == 0) red[t >> 5] = acc;
    __syncthreads();
    if (t == 0) {
        double E = red[0] + red[1] + red[2] + red[3] + red[4] + red[5] + red[6] + red[7];
        double Eold = g_Eprev;
        if (it >= 2 && fabs(E - Eold) <= 1e-8 * fabs(Eold)) {
            g_conv = 1;
            g_finalIt = it;
        }
        g_Eprev = E;
    }
}

// ---------------- final copy (select buffer by recorded parity) ----------------
__global__ void copy_out_kernel(float* __restrict__ out) {
    const float* src = (g_finalIt & 1) ? g_Ya : g_Yb;
    int i = (blockIdx.x * 256 + threadIdx.x) * 4;
    *(float4*)(out + i) = *(const float4*)(src + i);
}

// ---------------- host entry ----------------
extern "C" void kernel_launch(void* const* d_in, const int* in_sizes, int n_in,
                              void* d_out, int out_size) {
    const float* scores = (const float*)d_in[0];
    const float* feats  = (const float*)d_in[1];
    if (n_in >= 2 && in_sizes[0] == NROWS * FDIM) { // robustness to input order
        scores = (const float*)d_in[1];
        feats  = (const float*)d_in[0];
    }
    (void)out_size;

    init_kernel<<<1, 1>>>();
    normalize_kernel<<<NROWS, FDIM>>>(feats);
    unary_y0_kernel<<<NROWS / 8, 256>>>(scores);
    gemm_sym_kernel<<<NBLK * (NBLK + 1) / 2, 256>>>();
    topk_kernel<<<NROWS, 256>>>();
    for (int it = 0; it < MAXSTEPS; ++it) {
        iterA_kernel<<<NROWS / 8, 256>>>(it);
        iterB_kernel<<<1, 256>>>(it);
    }
    copy_out_kernel<<<NROWS * NCLS / (256 * 4), 256>>>((float*)d_out);
}